// round 9
// baseline (speedup 1.0000x reference)
#include <cuda_runtime.h>

#define NCLS 14
#define MAXP 32
#define MAXN 64
#define TPB  512     // 16 warps; first NWS scan, all 16 do pair loss
#define NW   (TPB / 32)
#define NWS  9       // scan warps -> 288 rows (validated sufficient; slow path exact)

// Single packed accumulator, zero-init. Layout:
//   bits [0:8)   warp-arrival counter (max NCLS*16 = 224)
//   bits [8:16)  active-class counter (max 14; warp 0 of each block only)
//   bits [16:64) loss sum, fixed point, scale 2^36 (exact, order-independent)
__device__ unsigned long long g_acc;

#define FX_SCALE 68719476736.0   // 2^36
#define ALLWARPS (NCLS * NW)     // 224

// branch-free softplus(x) = max(x,0) + log(1 + exp(-|x|)); MUFU only
__device__ __forceinline__ float softplus_fast(float x) {
    return fmaxf(x, 0.f) + __logf(1.f + __expf(-fabsf(x)));
}

__global__ __launch_bounds__(TPB)
void pauc_kernel(const float* __restrict__ logits,
                 const int*   __restrict__ targets,
                 float* __restrict__ out,
                 int Bn) {
    __shared__ float pos_buf[MAXP];
    __shared__ float neg_buf[MAXN];
    __shared__ int   cnt_sh[NWS];   // packed: pos | neg<<16
    __shared__ int   s_tp, s_tn;    // slow path only

    const int c    = blockIdx.x;          // class
    const int tid  = threadIdx.x;
    const int w    = tid >> 5;
    const int lane = tid & 31;
    const unsigned below = (1u << lane) - 1u;

    // ---- phase 1a: 9 warps ballot their own 32-row chunk in parallel ----
    int t = -1; float l = 0.f;
    unsigned pm = 0, nm = 0;
    if (w < NWS) {
        int row = w * 32 + lane;
        if (row < Bn) {
            t = targets[row * NCLS + c];
            l = logits [row * NCLS + c];
        }
        pm = __ballot_sync(0xffffffffu, t == 1);
        nm = __ballot_sync(0xffffffffu, t == 0);
        if (lane == 0) cnt_sh[w] = __popc(pm) | (__popc(nm) << 16);
    }
    __syncthreads();

    // every warp: one packed inclusive shuffle-scan over the 9 counts
    int pk = (lane < NWS) ? cnt_sh[lane] : 0;
#pragma unroll
    for (int off = 1; off < 16; off <<= 1) {
        int v = __shfl_up_sync(0xffffffffu, pk, off);
        if (lane >= off) pk += v;
    }
    const int tot = __shfl_sync(0xffffffffu, pk, NWS - 1);
    const int total_pos = tot & 0xFFFF;
    const int total_neg = tot >> 16;
    const int pre = (w == 0 || w >= NWS) ? 0 : __shfl_sync(0xffffffffu, pk, w - 1);

    // ordered write of matched entries at global first-k ranks
    if (t == 1) {
        int r = (pre & 0xFFFF) + __popc(pm & below);
        if (r < MAXP) pos_buf[r] = l;
    }
    if (t == 0) {
        int r = (pre >> 16) + __popc(nm & below);
        if (r < MAXN) neg_buf[r] = l;
    }

    // ---- phase 1b: uniform-branch slow path (statistically never) ----
    int tp, tn;
    const bool slow = (total_pos < MAXP) || (total_neg < MAXN);
    if (!slow) {
        tp = MAXP; tn = MAXN;
    } else {
        __syncthreads();            // fast-path buf writes visible
        if (w < 2) {
            const int   want = (w == 0) ? 1 : 0;
            const int   cap  = (w == 0) ? MAXP : MAXN;
            float*      buf  = (w == 0) ? pos_buf : neg_buf;
            int cnt = (w == 0) ? total_pos : total_neg;
            int base = NWS * 32;
            while (cnt < cap && base < Bn) {
                int row2 = base + lane;
                int t2 = -1; float l2 = 0.f;
                if (row2 < Bn) {
                    t2 = targets[row2 * NCLS + c];
                    l2 = logits [row2 * NCLS + c];
                }
                unsigned m = __ballot_sync(0xffffffffu, t2 == want);
                if (t2 == want) {
                    int r = cnt + __popc(m & below);
                    if (r < cap) buf[r] = l2;
                }
                cnt += __popc(m);
                base += 32;
            }
            if (lane == 0) {
                if (w == 0) s_tp = min(cnt, MAXP);
                else        s_tn = min(cnt, MAXN);
            }
        }
    }
    __syncthreads();
    if (slow) { tp = s_tp; tn = s_tn; }

    // ---- phase 2: all 16 warps share the tp x tn pair loss ----
    float s0, s1, s2, s3;
    if (tp == MAXP && tn == MAXN) {
        // common case: 2048 pairs, 4 per thread, 4 independent MUFU chains
        const int i0 = tid;
        const int i1 = tid + TPB;
        const int i2 = tid + 2 * TPB;
        const int i3 = tid + 3 * TPB;
        s0 = softplus_fast(neg_buf[i0 & (MAXN - 1)] - pos_buf[i0 >> 6]);
        s1 = softplus_fast(neg_buf[i1 & (MAXN - 1)] - pos_buf[i1 >> 6]);
        s2 = softplus_fast(neg_buf[i2 & (MAXN - 1)] - pos_buf[i2 >> 6]);
        s3 = softplus_fast(neg_buf[i3 & (MAXN - 1)] - pos_buf[i3 >> 6]);
    } else {
        s0 = s1 = s2 = s3 = 0.f;
        const int total = tp * tn;
        for (int idx = tid; idx < total; idx += TPB) {
            int i = idx / tn;
            int j = idx - i * tn;
            s0 += softplus_fast(neg_buf[j] - pos_buf[i]);
        }
    }
    float s = (s0 + s1) + (s2 + s3);
#pragma unroll
    for (int off = 16; off; off >>= 1)
        s += __shfl_xor_sync(0xffffffffu, s, off);

    // ---- phase 3: per-warp packed atomic; last arriving warp finalizes ----
    if (lane == 0) {
        const bool act = (tp > 0) && (tn > 0);
        float part = act ? s / (float)max(tp * tn, 1) : 0.f;

        unsigned long long fx = (unsigned long long)((double)part * FX_SCALE + 0.5);
        unsigned long long pkt = 1ull
                               | ((unsigned long long)((w == 0 && act) ? 1 : 0) << 8)
                               | (fx << 16);
        unsigned long long totacc = atomicAdd(&g_acc, pkt) + pkt;
        if ((totacc & 0xFFull) == (unsigned long long)ALLWARPS) { // last warp
            unsigned cnt = (unsigned)((totacc >> 8) & 0xFFull);
            double ls = (double)(totacc >> 16) * (1.0 / FX_SCALE);
            out[0] = (cnt > 0) ? (float)(ls / (double)cnt) : 0.f;
            // reset for next graph replay; all other warps' atomics have
            // completed (count==ALLWARPS), and kernel-completion ordering
            // publishes this store before the next launch
            g_acc = 0ull;
        }
    }
}

extern "C" void kernel_launch(void* const* d_in, const int* in_sizes, int n_in,
                              void* d_out, int out_size) {
    const float* logits  = (const float*)d_in[0];
    const int*   targets = (const int*)  d_in[1];
    float*       out     = (float*)d_out;
    int Bn = in_sizes[0] / NCLS;
    pauc_kernel<<<NCLS, TPB>>>(logits, targets, out, Bn);
}

// round 10
// speedup vs baseline: 1.3204x; 1.3204x over previous
#include <cuda_runtime.h>

#define NCLS 14
#define MAXP 32
#define MAXN 64
#define TPB  512     // 16 warps: warp w scans rows [32w, 32w+32)
#define NW   (TPB / 32)

// Single packed accumulator, zero-init. Layout:
//   bits [0:8)   warp-arrival counter (max NCLS*16 = 224)
//   bits [8:16)  active-class counter (max 14; warp 0 of each block only)
//   bits [16:64) loss sum, fixed point, scale 2^36 (exact, order-independent)
__device__ unsigned long long g_acc;

#define FX_SCALE 68719476736.0   // 2^36
#define ALLWARPS (NCLS * NW)     // 224

// branch-free softplus(x) = max(x,0) + log(1 + exp(-|x|)); MUFU only
__device__ __forceinline__ float softplus_fast(float x) {
    return fmaxf(x, 0.f) + __logf(1.f + __expf(-fabsf(x)));
}

__global__ __launch_bounds__(TPB)
void pauc_kernel(const float* __restrict__ logits,
                 const int*   __restrict__ targets,
                 float* __restrict__ out,
                 int Bn) {
    __shared__ float pos_buf[MAXP];
    __shared__ float neg_buf[MAXN];
    __shared__ int   cnt_sh[NW];    // packed: pos | neg<<16
    __shared__ int   s_tp, s_tn;    // slow path only

    const int c    = blockIdx.x;          // class
    const int tid  = threadIdx.x;
    const int w    = tid >> 5;
    const int lane = tid & 31;
    const unsigned below = (1u << lane) - 1u;

    // ---- phase 1a: all 16 warps ballot their own 32-row chunk in parallel ----
    int row = w * 32 + lane;
    int t = -1; float l = 0.f;
    if (row < Bn) {
        t = targets[row * NCLS + c];
        l = logits [row * NCLS + c];
    }
    unsigned pm = __ballot_sync(0xffffffffu, t == 1);
    unsigned nm = __ballot_sync(0xffffffffu, t == 0);
    if (lane == 0) cnt_sh[w] = __popc(pm) | (__popc(nm) << 16);
    __syncthreads();

    // every warp: one packed inclusive shuffle-scan over the 16 counts
    int pk = (lane < NW) ? cnt_sh[lane] : 0;
#pragma unroll
    for (int off = 1; off < NW; off <<= 1) {
        int v = __shfl_up_sync(0xffffffffu, pk, off);
        if (lane >= off) pk += v;
    }
    const int tot = __shfl_sync(0xffffffffu, pk, NW - 1);
    const int total_pos = tot & 0xFFFF;
    const int total_neg = tot >> 16;
    const int pre = (w == 0) ? 0 : __shfl_sync(0xffffffffu, pk, w - 1);

    // ordered write of matched entries at global first-k ranks
    if (t == 1) {
        int r = (pre & 0xFFFF) + __popc(pm & below);
        if (r < MAXP) pos_buf[r] = l;
    }
    if (t == 0) {
        int r = (pre >> 16) + __popc(nm & below);
        if (r < MAXN) neg_buf[r] = l;
    }

    // ---- phase 1b: uniform-branch slow path (statistically never) ----
    int tp, tn;
    const bool slow = (total_pos < MAXP) || (total_neg < MAXN);
    if (!slow) {
        tp = MAXP; tn = MAXN;
    } else {
        __syncthreads();            // fast-path buf writes visible
        if (w < 2) {
            const int   want = (w == 0) ? 1 : 0;
            const int   cap  = (w == 0) ? MAXP : MAXN;
            float*      buf  = (w == 0) ? pos_buf : neg_buf;
            int cnt = (w == 0) ? total_pos : total_neg;
            int base = NW * 32;
            while (cnt < cap && base < Bn) {
                int row2 = base + lane;
                int t2 = -1; float l2 = 0.f;
                if (row2 < Bn) {
                    t2 = targets[row2 * NCLS + c];
                    l2 = logits [row2 * NCLS + c];
                }
                unsigned m = __ballot_sync(0xffffffffu, t2 == want);
                if (t2 == want) {
                    int r = cnt + __popc(m & below);
                    if (r < cap) buf[r] = l2;
                }
                cnt += __popc(m);
                base += 32;
            }
            if (lane == 0) {
                if (w == 0) s_tp = min(cnt, MAXP);
                else        s_tn = min(cnt, MAXN);
            }
        }
    }
    __syncthreads();
    if (slow) { tp = s_tp; tn = s_tn; }

    // ---- phase 2: all 16 warps share the tp x tn pair loss ----
    float s0, s1, s2, s3;
    if (tp == MAXP && tn == MAXN) {
        // common case: 2048 pairs, 4 per thread, 4 independent MUFU chains
        const int i0 = tid;
        const int i1 = tid + TPB;
        const int i2 = tid + 2 * TPB;
        const int i3 = tid + 3 * TPB;
        s0 = softplus_fast(neg_buf[i0 & (MAXN - 1)] - pos_buf[i0 >> 6]);
        s1 = softplus_fast(neg_buf[i1 & (MAXN - 1)] - pos_buf[i1 >> 6]);
        s2 = softplus_fast(neg_buf[i2 & (MAXN - 1)] - pos_buf[i2 >> 6]);
        s3 = softplus_fast(neg_buf[i3 & (MAXN - 1)] - pos_buf[i3 >> 6]);
    } else {
        s0 = s1 = s2 = s3 = 0.f;
        const int total = tp * tn;
        for (int idx = tid; idx < total; idx += TPB) {
            int i = idx / tn;
            int j = idx - i * tn;
            s0 += softplus_fast(neg_buf[j] - pos_buf[i]);
        }
    }
    float s = (s0 + s1) + (s2 + s3);
#pragma unroll
    for (int off = 16; off; off >>= 1)
        s += __shfl_xor_sync(0xffffffffu, s, off);

    // ---- phase 3: per-warp packed atomic; last arriving warp finalizes ----
    if (lane == 0) {
        const bool act = (tp > 0) && (tn > 0);
        float part = act ? s / (float)max(tp * tn, 1) : 0.f;

        unsigned long long fx = (unsigned long long)((double)part * FX_SCALE + 0.5);
        unsigned long long pkt = 1ull
                               | ((unsigned long long)((w == 0 && act) ? 1 : 0) << 8)
                               | (fx << 16);
        unsigned long long totacc = atomicAdd(&g_acc, pkt) + pkt;
        if ((totacc & 0xFFull) == (unsigned long long)ALLWARPS) { // last warp
            unsigned cnt = (unsigned)((totacc >> 8) & 0xFFull);
            double ls = (double)(totacc >> 16) * (1.0 / FX_SCALE);
            out[0] = (cnt > 0) ? (float)(ls / (double)cnt) : 0.f;
            // reset for next graph replay; all other warps' atomics have
            // completed (count==ALLWARPS), and kernel-completion ordering
            // publishes this store before the next launch
            g_acc = 0ull;
        }
    }
}

extern "C" void kernel_launch(void* const* d_in, const int* in_sizes, int n_in,
                              void* d_out, int out_size) {
    const float* logits  = (const float*)d_in[0];
    const int*   targets = (const int*)  d_in[1];
    float*       out     = (float*)d_out;
    int Bn = in_sizes[0] / NCLS;
    pauc_kernel<<<NCLS, TPB>>>(logits, targets, out, Bn);
}